// round 1
// baseline (speedup 1.0000x reference)
#include <cuda_runtime.h>
#include <math.h>

#define NB   8
#define SEQ  4096
#define DM   512
#define DKV  64
#define ROWS (NB*SEQ)          // 32768
#define SMSTRIDE 68            // 64 + 4 pad, keeps float4 alignment + kills bank conflicts

// Scratch for projected q/k/v (allocation-free rule: __device__ globals)
__device__ float g_qp[ROWS*DKV];
__device__ float g_kp[ROWS*DKV];
__device__ float g_vp[ROWS*DKV];

// ---------------------------------------------------------------------------
// Projection: out[r,e] = sum_d x[r,d]*W[d,e] + b[e].  M=32768, K=512, N=64.
// 64x64 output tile per block, 256 threads, 4x4 microtile per thread.
// ---------------------------------------------------------------------------
__global__ __launch_bounds__(256) void proj_kernel(
    const float* __restrict__ q, const float* __restrict__ k, const float* __restrict__ v,
    const float* __restrict__ Wq, const float* __restrict__ bq,
    const float* __restrict__ Wk, const float* __restrict__ bk,
    const float* __restrict__ Wv, const float* __restrict__ bv)
{
    __shared__ float Xs[64][SMSTRIDE];
    __shared__ float Ws[64][SMSTRIDE];

    const int which = blockIdx.z;
    const float* x    = (which == 0) ? q  : (which == 1) ? k  : v;
    const float* W    = (which == 0) ? Wq : (which == 1) ? Wk : Wv;
    const float* bias = (which == 0) ? bq : (which == 1) ? bk : bv;
    float* outp       = (which == 0) ? g_qp : (which == 1) ? g_kp : g_vp;

    const int t  = threadIdx.x;
    const int tx = t & 15;
    const int ty = t >> 4;
    const int rowbase = blockIdx.x * 64;

    float acc[4][4];
#pragma unroll
    for (int i = 0; i < 4; i++)
#pragma unroll
        for (int j = 0; j < 4; j++) acc[i][j] = 0.0f;

    for (int kc = 0; kc < DM; kc += 64) {
#pragma unroll
        for (int i = 0; i < 4; i++) {
            int f  = t + i * 256;          // float4 slot 0..1023
            int r  = f >> 4;
            int c4 = (f & 15) << 2;
            *(float4*)&Xs[r][c4] = *(const float4*)&x[(size_t)(rowbase + r) * DM + kc + c4];
            *(float4*)&Ws[r][c4] = *(const float4*)&W[(size_t)(kc + r) * DKV + c4];
        }
        __syncthreads();
#pragma unroll 8
        for (int d = 0; d < 64; d++) {
            float4 b4 = *(float4*)&Ws[d][tx << 2];
            float a0 = Xs[(ty << 2) + 0][d];
            float a1 = Xs[(ty << 2) + 1][d];
            float a2 = Xs[(ty << 2) + 2][d];
            float a3 = Xs[(ty << 2) + 3][d];
            acc[0][0] += a0 * b4.x; acc[0][1] += a0 * b4.y; acc[0][2] += a0 * b4.z; acc[0][3] += a0 * b4.w;
            acc[1][0] += a1 * b4.x; acc[1][1] += a1 * b4.y; acc[1][2] += a1 * b4.z; acc[1][3] += a1 * b4.w;
            acc[2][0] += a2 * b4.x; acc[2][1] += a2 * b4.y; acc[2][2] += a2 * b4.z; acc[2][3] += a2 * b4.w;
            acc[3][0] += a3 * b4.x; acc[3][1] += a3 * b4.y; acc[3][2] += a3 * b4.z; acc[3][3] += a3 * b4.w;
        }
        __syncthreads();
    }

    float4 bb = *(const float4*)&bias[tx << 2];
#pragma unroll
    for (int i = 0; i < 4; i++) {
        float4 r;
        r.x = acc[i][0] + bb.x;
        r.y = acc[i][1] + bb.y;
        r.z = acc[i][2] + bb.z;
        r.w = acc[i][3] + bb.w;
        *(float4*)&outp[(size_t)(rowbase + (ty << 2) + i) * DKV + (tx << 2)] = r;
    }
}

// ---------------------------------------------------------------------------
// Flash attention: per block, 64 query rows of one batch; loop 64 KV tiles.
// Online softmax; fp32 accumulation throughout.
// ---------------------------------------------------------------------------
__global__ __launch_bounds__(256) void flash_kernel(const int* __restrict__ maskp,
                                                    float* __restrict__ out)
{
    extern __shared__ float sm[];
    float* Qs  = sm;                      // [64][68]  q rows (row-major)
    float* Kst = Qs  + 64 * SMSTRIDE;     // [64][68]  K tile, d-major: Kst[d][j]
    float* Vs  = Kst + 64 * SMSTRIDE;     // [64][68]  V tile, row-major: Vs[j][d]
    float* Ps  = Vs  + 64 * SMSTRIDE;     // [64][68]  P tile (softmax probs)

    const int t  = threadIdx.x;
    const int tx = t & 15;
    const int ty = t >> 4;
    const int bz    = blockIdx.y;
    const int qbase = bz * SEQ + blockIdx.x * 64;

    const float maskval = (float)(*maskp);   // bits 0 either encoding -> 0.0f
    const float scale   = 0.125f;            // 1/sqrt(64)

    // Load Q tile once
#pragma unroll
    for (int i = 0; i < 4; i++) {
        int f  = t + i * 256;
        int r  = f >> 4;
        int c4 = (f & 15) << 2;
        *(float4*)&Qs[r * SMSTRIDE + c4] =
            *(const float4*)&g_qp[(size_t)(qbase + r) * DKV + c4];
    }

    float m[4], l[4], o[4][4];
#pragma unroll
    for (int i = 0; i < 4; i++) {
        m[i] = -INFINITY; l[i] = 0.0f;
#pragma unroll
        for (int c = 0; c < 4; c++) o[i][c] = 0.0f;
    }

    for (int kt = 0; kt < SEQ / 64; kt++) {
        const int kb = bz * SEQ + kt * 64;
        __syncthreads();   // prior O-accum / Q store visible before tiles overwritten
#pragma unroll
        for (int i = 0; i < 4; i++) {
            int f  = t + i * 256;
            int r  = f >> 4;
            int c4 = (f & 15) << 2;
            float4 kv = *(const float4*)&g_kp[(size_t)(kb + r) * DKV + c4];
            Kst[(c4 + 0) * SMSTRIDE + r] = kv.x;
            Kst[(c4 + 1) * SMSTRIDE + r] = kv.y;
            Kst[(c4 + 2) * SMSTRIDE + r] = kv.z;
            Kst[(c4 + 3) * SMSTRIDE + r] = kv.w;
            *(float4*)&Vs[r * SMSTRIDE + c4] =
                *(const float4*)&g_vp[(size_t)(kb + r) * DKV + c4];
        }
        __syncthreads();

        // S = Q @ K^T  (4x4 microtile)
        float s[4][4];
#pragma unroll
        for (int i = 0; i < 4; i++)
#pragma unroll
            for (int j = 0; j < 4; j++) s[i][j] = 0.0f;

#pragma unroll 8
        for (int d = 0; d < 64; d++) {
            float4 b4 = *(float4*)&Kst[d * SMSTRIDE + (tx << 2)];
            float a0 = Qs[((ty << 2) + 0) * SMSTRIDE + d];
            float a1 = Qs[((ty << 2) + 1) * SMSTRIDE + d];
            float a2 = Qs[((ty << 2) + 2) * SMSTRIDE + d];
            float a3 = Qs[((ty << 2) + 3) * SMSTRIDE + d];
            s[0][0] += a0 * b4.x; s[0][1] += a0 * b4.y; s[0][2] += a0 * b4.z; s[0][3] += a0 * b4.w;
            s[1][0] += a1 * b4.x; s[1][1] += a1 * b4.y; s[1][2] += a1 * b4.z; s[1][3] += a1 * b4.w;
            s[2][0] += a2 * b4.x; s[2][1] += a2 * b4.y; s[2][2] += a2 * b4.z; s[2][3] += a2 * b4.w;
            s[3][0] += a3 * b4.x; s[3][1] += a3 * b4.y; s[3][2] += a3 * b4.z; s[3][3] += a3 * b4.w;
        }

        // scale + equality mask + online softmax
#pragma unroll
        for (int i = 0; i < 4; i++) {
#pragma unroll
            for (int j = 0; j < 4; j++) {
                float v = s[i][j] * scale;
                if (v == maskval) v = -INFINITY;
                s[i][j] = v;
            }
            float mx = fmaxf(fmaxf(s[i][0], s[i][1]), fmaxf(s[i][2], s[i][3]));
            mx = fmaxf(mx, __shfl_xor_sync(0xffffffffu, mx, 1));
            mx = fmaxf(mx, __shfl_xor_sync(0xffffffffu, mx, 2));
            mx = fmaxf(mx, __shfl_xor_sync(0xffffffffu, mx, 4));
            mx = fmaxf(mx, __shfl_xor_sync(0xffffffffu, mx, 8));
            float mnew = fmaxf(m[i], mx);
            float corr = __expf(m[i] - mnew);   // m=-inf first tile -> 0
            m[i] = mnew;
            float rs = 0.0f;
#pragma unroll
            for (int j = 0; j < 4; j++) {
                float p = __expf(s[i][j] - mnew);
                s[i][j] = p;
                rs += p;
            }
            rs += __shfl_xor_sync(0xffffffffu, rs, 1);
            rs += __shfl_xor_sync(0xffffffffu, rs, 2);
            rs += __shfl_xor_sync(0xffffffffu, rs, 4);
            rs += __shfl_xor_sync(0xffffffffu, rs, 8);
            l[i] = l[i] * corr + rs;
#pragma unroll
            for (int c = 0; c < 4; c++) o[i][c] *= corr;
#pragma unroll
            for (int j = 0; j < 4; j++)
                Ps[((ty << 2) + i) * SMSTRIDE + (tx << 2) + j] = s[i][j];
        }
        __syncthreads();

        // O += P @ V
#pragma unroll 8
        for (int j = 0; j < 64; j++) {
            float4 v4 = *(float4*)&Vs[j * SMSTRIDE + (tx << 2)];
            float a0 = Ps[((ty << 2) + 0) * SMSTRIDE + j];
            float a1 = Ps[((ty << 2) + 1) * SMSTRIDE + j];
            float a2 = Ps[((ty << 2) + 2) * SMSTRIDE + j];
            float a3 = Ps[((ty << 2) + 3) * SMSTRIDE + j];
            o[0][0] += a0 * v4.x; o[0][1] += a0 * v4.y; o[0][2] += a0 * v4.z; o[0][3] += a0 * v4.w;
            o[1][0] += a1 * v4.x; o[1][1] += a1 * v4.y; o[1][2] += a1 * v4.z; o[1][3] += a1 * v4.w;
            o[2][0] += a2 * v4.x; o[2][1] += a2 * v4.y; o[2][2] += a2 * v4.z; o[2][3] += a2 * v4.w;
            o[3][0] += a3 * v4.x; o[3][1] += a3 * v4.y; o[3][2] += a3 * v4.z; o[3][3] += a3 * v4.w;
        }
    }

    // normalize + store
#pragma unroll
    for (int i = 0; i < 4; i++) {
        float inv = 1.0f / l[i];
        float4 r;
        r.x = o[i][0] * inv; r.y = o[i][1] * inv; r.z = o[i][2] * inv; r.w = o[i][3] * inv;
        *(float4*)&out[(size_t)(qbase + (ty << 2) + i) * DKV + (tx << 2)] = r;
    }
}

// ---------------------------------------------------------------------------
extern "C" void kernel_launch(void* const* d_in, const int* in_sizes, int n_in,
                              void* d_out, int out_size)
{
    const float* q  = (const float*)d_in[0];
    const float* k  = (const float*)d_in[1];
    const float* v  = (const float*)d_in[2];
    const float* Wq = (const float*)d_in[3];
    const float* bq = (const float*)d_in[4];
    const float* Wk = (const float*)d_in[5];
    const float* bk = (const float*)d_in[6];
    const float* Wv = (const float*)d_in[7];
    const float* bv = (const float*)d_in[8];
    const int*   mk = (const int*)d_in[9];
    float* out = (float*)d_out;

    // projections: 512 row-tiles x 3 matrices
    dim3 pgrid(ROWS / 64, 1, 3);
    proj_kernel<<<pgrid, 256>>>(q, k, v, Wq, bq, Wk, bk, Wv, bv);

    // flash attention
    size_t smem = (size_t)4 * 64 * SMSTRIDE * sizeof(float);   // 69632 B
    cudaFuncSetAttribute(flash_kernel, cudaFuncAttributeMaxDynamicSharedMemorySize,
                         (int)smem);
    dim3 fgrid(SEQ / 64, NB);
    flash_kernel<<<fgrid, 256, smem>>>(mk, out);
}

// round 4
// speedup vs baseline: 2.4898x; 2.4898x over previous
#include <cuda_runtime.h>
#include <cuda_bf16.h>
#include <math.h>
#include <stdint.h>

#define NB   8
#define SEQ  4096
#define DM   512
#define DKV  64
#define ROWS (NB*SEQ)
#define SK   72          // smem row stride (elements): 72 = 64 + 8, rotates banks by 4/row

// Split-precision projected tensors (allocation-free rule: device globals)
__device__ __nv_bfloat16 g_q_hi[ROWS*DKV];
__device__ __nv_bfloat16 g_q_lo[ROWS*DKV];
__device__ __nv_bfloat16 g_k_hi[ROWS*DKV];
__device__ __nv_bfloat16 g_k_lo[ROWS*DKV];
__device__ __nv_bfloat16 g_vt_hi[ROWS*DKV];   // transposed: [b][dv][n]
__device__ __nv_bfloat16 g_vt_lo[ROWS*DKV];

// ---------------------------------------------------------------- helpers
__device__ __forceinline__ uint32_t smem_u32(const void* p){
    uint32_t a;
    asm("{ .reg .u64 t; cvta.to.shared.u64 t, %1; cvt.u32.u64 %0, t; }" : "=r"(a) : "l"(p));
    return a;
}
__device__ __forceinline__ uint32_t pack2bf(__nv_bfloat16 a, __nv_bfloat16 b){
    return (uint32_t)__bfloat16_as_ushort(a) | ((uint32_t)__bfloat16_as_ushort(b) << 16);
}
// split two floats into packed bf16 hi + packed bf16 residual
__device__ __forceinline__ uint32_t split2(float a, float b, uint32_t& lo){
    __nv_bfloat16 ha = __float2bfloat16(a), hb = __float2bfloat16(b);
    __nv_bfloat16 la = __float2bfloat16(a - __bfloat162float(ha));
    __nv_bfloat16 lb = __float2bfloat16(b - __bfloat162float(hb));
    lo = pack2bf(la, lb);
    return pack2bf(ha, hb);
}
// m16n8k16 row.col bf16 -> f32 accum (HMMA; baseline PTX, works on sm_100)
__device__ __forceinline__ void mma_bf16(float* c, const uint32_t* a, const uint32_t* b){
    asm volatile("mma.sync.aligned.m16n8k16.row.col.f32.bf16.bf16.f32 "
        "{%0,%1,%2,%3}, {%4,%5,%6,%7}, {%8,%9}, {%0,%1,%2,%3};"
        : "+f"(c[0]), "+f"(c[1]), "+f"(c[2]), "+f"(c[3])
        : "r"(a[0]), "r"(a[1]), "r"(a[2]), "r"(a[3]), "r"(b[0]), "r"(b[1]));
}
__device__ __forceinline__ void cpa16(uint32_t dst, const void* src){
    asm volatile("cp.async.ca.shared.global [%0], [%1], 16;" :: "r"(dst), "l"(src));
}
#define CPCOMMIT() asm volatile("cp.async.commit_group;" ::: "memory")
#define CPWAIT0()  asm volatile("cp.async.wait_group 0;" ::: "memory")

// ============================================================================
// Projection: X[32768,512] @ W[512,64] + b -> bf16 hi/lo (V transposed)
// grid (256,1,3), 256 thr, 8 warps as 4m x 2n (32x32 tiles).
// smem: XH@0 XL@18432 | WH@36864 WL@46080 | bias@55296 | OS(f32)@55552  total 92416
// ============================================================================
#define P_SMEM 92416

__global__ __launch_bounds__(256, 2) void projm(
    const float* __restrict__ q, const float* __restrict__ k, const float* __restrict__ v,
    const float* __restrict__ Wq, const float* __restrict__ bq,
    const float* __restrict__ Wk, const float* __restrict__ bk,
    const float* __restrict__ Wv, const float* __restrict__ bv)
{
    extern __shared__ __align__(16) char sm[];
    const int t = threadIdx.x, lane = t & 31, wid = t >> 5;
    const int warpm = wid >> 1, warpn = wid & 1;
    const int g = lane >> 2, tig = lane & 3;
    const int which = blockIdx.z;
    const int rowbase = blockIdx.x * 128;
    const float* x    = which == 0 ? q  : which == 1 ? k  : v;
    const float* W    = which == 0 ? Wq : which == 1 ? Wk : Wv;
    const float* bias = which == 0 ? bq : which == 1 ? bk : bv;

    float* biasS = (float*)(sm + 55296);
    if (t < 64) biasS[t] = bias[t];

    float acc[2][4][4];
#pragma unroll
    for (int mt = 0; mt < 2; mt++)
#pragma unroll
        for (int nt = 0; nt < 4; nt++)
#pragma unroll
            for (int u = 0; u < 4; u++) acc[mt][nt][u] = 0.f;

    for (int kc = 0; kc < 8; kc++){
        __syncthreads();
        // X chunk 128x64 f32 -> hi/lo bf16
#pragma unroll
        for (int i = 0; i < 8; i++){
            int idx = t + i*256, r = idx >> 4, c0 = (idx & 15) * 4;
            float4 xv = *(const float4*)(x + (size_t)(rowbase + r)*DM + kc*64 + c0);
            uint32_t lo0, lo1;
            uint32_t h0 = split2(xv.x, xv.y, lo0);
            uint32_t h1 = split2(xv.z, xv.w, lo1);
            *(uint2*)(sm + 0     + (r*SK + c0)*2) = make_uint2(h0, h1);
            *(uint2*)(sm + 18432 + (r*SK + c0)*2) = make_uint2(lo0, lo1);
        }
        // W chunk 64x64 -> transposed Wt[n][k] hi/lo
#pragma unroll
        for (int i = 0; i < 4; i++){
            int idx = t + i*256, kk = idx >> 4, n0 = (idx & 15) * 4;
            float4 wv = *(const float4*)(W + (size_t)(kc*64 + kk)*DKV + n0);
#pragma unroll
            for (int u = 0; u < 4; u++){
                float val = (&wv.x)[u];
                __nv_bfloat16 h = __float2bfloat16(val);
                __nv_bfloat16 l = __float2bfloat16(val - __bfloat162float(h));
                *(unsigned short*)(sm + 36864 + ((n0+u)*SK + kk)*2) = __bfloat16_as_ushort(h);
                *(unsigned short*)(sm + 46080 + ((n0+u)*SK + kk)*2) = __bfloat16_as_ushort(l);
            }
        }
        __syncthreads();
#pragma unroll
        for (int ks = 0; ks < 4; ks++){
            const int k0 = ks*16 + 2*tig;
            uint32_t ah[2][4], al[2][4], bh[4][2], bl[4][2];
#pragma unroll
            for (int mt = 0; mt < 2; mt++){
                int r0 = warpm*32 + mt*16;
                ah[mt][0] = *(const uint32_t*)(sm + 0 + ((r0+g  )*SK + k0    )*2);
                ah[mt][1] = *(const uint32_t*)(sm + 0 + ((r0+g+8)*SK + k0    )*2);
                ah[mt][2] = *(const uint32_t*)(sm + 0 + ((r0+g  )*SK + k0 + 8)*2);
                ah[mt][3] = *(const uint32_t*)(sm + 0 + ((r0+g+8)*SK + k0 + 8)*2);
                al[mt][0] = *(const uint32_t*)(sm + 18432 + ((r0+g  )*SK + k0    )*2);
                al[mt][1] = *(const uint32_t*)(sm + 18432 + ((r0+g+8)*SK + k0    )*2);
                al[mt][2] = *(const uint32_t*)(sm + 18432 + ((r0+g  )*SK + k0 + 8)*2);
                al[mt][3] = *(const uint32_t*)(sm + 18432 + ((r0+g+8)*SK + k0 + 8)*2);
            }
#pragma unroll
            for (int nt = 0; nt < 4; nt++){
                int n = warpn*32 + nt*8 + g;
                bh[nt][0] = *(const uint32_t*)(sm + 36864 + (n*SK + k0    )*2);
                bh[nt][1] = *(const uint32_t*)(sm + 36864 + (n*SK + k0 + 8)*2);
                bl[nt][0] = *(const uint32_t*)(sm + 46080 + (n*SK + k0    )*2);
                bl[nt][1] = *(const uint32_t*)(sm + 46080 + (n*SK + k0 + 8)*2);
            }
#pragma unroll
            for (int mt = 0; mt < 2; mt++)
#pragma unroll
                for (int nt = 0; nt < 4; nt++){
                    mma_bf16(acc[mt][nt], ah[mt], bh[nt]);
                    mma_bf16(acc[mt][nt], al[mt], bh[nt]);
                    mma_bf16(acc[mt][nt], ah[mt], bl[nt]);
                }
        }
    }
    // epilogue
    if (which < 2){
        __nv_bfloat16* gh = which == 0 ? g_q_hi : g_k_hi;
        __nv_bfloat16* gl = which == 0 ? g_q_lo : g_k_lo;
#pragma unroll
        for (int mt = 0; mt < 2; mt++){
            int r0 = warpm*32 + mt*16;
#pragma unroll
            for (int nt = 0; nt < 4; nt++){
                int c0 = warpn*32 + nt*8 + 2*tig;
                float b0 = biasS[c0], b1 = biasS[c0+1];
                uint32_t lo, hi;
                hi = split2(acc[mt][nt][0] + b0, acc[mt][nt][1] + b1, lo);
                *(uint32_t*)((char*)gh + ((size_t)(rowbase + r0 + g)*DKV + c0)*2) = hi;
                *(uint32_t*)((char*)gl + ((size_t)(rowbase + r0 + g)*DKV + c0)*2) = lo;
                hi = split2(acc[mt][nt][2] + b0, acc[mt][nt][3] + b1, lo);
                *(uint32_t*)((char*)gh + ((size_t)(rowbase + r0 + g + 8)*DKV + c0)*2) = hi;
                *(uint32_t*)((char*)gl + ((size_t)(rowbase + r0 + g + 8)*DKV + c0)*2) = lo;
            }
        }
    } else {
        float* OS = (float*)(sm + 55552);
#pragma unroll
        for (int mt = 0; mt < 2; mt++){
            int r0 = warpm*32 + mt*16;
#pragma unroll
            for (int nt = 0; nt < 4; nt++){
                int c0 = warpn*32 + nt*8 + 2*tig;
                float b0 = biasS[c0], b1 = biasS[c0+1];
                *(float2*)(OS + (r0+g  )*SK + c0) = make_float2(acc[mt][nt][0]+b0, acc[mt][nt][1]+b1);
                *(float2*)(OS + (r0+g+8)*SK + c0) = make_float2(acc[mt][nt][2]+b0, acc[mt][nt][3]+b1);
            }
        }
        __syncthreads();
        int bb = rowbase >> 12, n0 = rowbase & 4095;
        int dv = t >> 2, q4 = t & 3;
#pragma unroll
        for (int rr = 0; rr < 16; rr++){
            int r = q4*32 + rr*2;
            float v0 = OS[r*SK + dv], v1 = OS[(r+1)*SK + dv];
            uint32_t lo, hi = split2(v0, v1, lo);
            size_t go = ((size_t)bb*DKV + dv)*SEQ + n0 + r;
            *(uint32_t*)((char*)g_vt_hi + go*2) = hi;
            *(uint32_t*)((char*)g_vt_lo + go*2) = lo;
        }
    }
}

// ============================================================================
// Flash attention (HMMA). grid (32,8), 256 thr, 8 warps as 4m x 2n.
// smem bytes: K[2]{hi,lo}@0 (36864) | V[2]{hi,lo}@36864 (36864) |
//             PH@73728 PL@92160 | lred@110592   total 111104
// ============================================================================
#define F_SMEM 111104

__device__ __forceinline__ void kvload(uint32_t smb, int t, int b, int kt, int buf){
    const int kb = kt * 64;
    const __nv_bfloat16* skh = g_k_hi  + ((size_t)b*SEQ + kb)*DKV;
    const __nv_bfloat16* skl = g_k_lo  + ((size_t)b*SEQ + kb)*DKV;
    const __nv_bfloat16* svh = g_vt_hi + (size_t)b*DKV*SEQ + kb;
    const __nv_bfloat16* svl = g_vt_lo + (size_t)b*DKV*SEQ + kb;
#pragma unroll
    for (int i = 0; i < 2; i++){
        int idx = t + i*256, r = idx >> 3, c0 = (idx & 7) * 8;
        uint32_t off = (uint32_t)(r*SK + c0)*2;
        cpa16(smb + buf*18432          + off, skh + (size_t)r*DKV + c0);
        cpa16(smb + buf*18432 + 9216   + off, skl + (size_t)r*DKV + c0);
        cpa16(smb + 36864 + buf*18432        + off, svh + (size_t)r*SEQ + c0);
        cpa16(smb + 36864 + buf*18432 + 9216 + off, svl + (size_t)r*SEQ + c0);
    }
    CPCOMMIT();
}

__global__ __launch_bounds__(256, 1) void flashm(const int* __restrict__ maskp,
                                                 float* __restrict__ out)
{
    extern __shared__ __align__(16) char sm[];
    const uint32_t smb = smem_u32(sm);
    const int t = threadIdx.x, lane = t & 31, wid = t >> 5;
    const int warpm = wid >> 1, warpn = wid & 1;
    const int g = lane >> 2, tig = lane & 3;
    const int b = blockIdx.y;
    const size_t qbase = (size_t)b*SEQ + (size_t)blockIdx.x*128;
    const float maskv = (float)(*maskp);

    if (t < 128) *(float*)(sm + 110592 + t*4) = 0.f;

    // stage Q hi/lo into P area, then load fragments to registers
    {
        const __nv_bfloat16* qh = g_q_hi + qbase*DKV;
        const __nv_bfloat16* ql = g_q_lo + qbase*DKV;
#pragma unroll
        for (int i = 0; i < 4; i++){
            int idx = t + i*256, r = idx >> 3, c0 = (idx & 7) * 8;
            *(uint4*)(sm + 73728 + (r*SK + c0)*2) = *(const uint4*)(qh + (size_t)r*DKV + c0);
            *(uint4*)(sm + 92160 + (r*SK + c0)*2) = *(const uint4*)(ql + (size_t)r*DKV + c0);
        }
    }
    __syncthreads();
    uint32_t qfh[2][4][4], qfl[2][4][4];
#pragma unroll
    for (int mt = 0; mt < 2; mt++){
        int r0 = warpm*32 + mt*16;
#pragma unroll
        for (int ks = 0; ks < 4; ks++){
            int k0 = ks*16 + 2*tig;
            qfh[mt][ks][0] = *(const uint32_t*)(sm + 73728 + ((r0+g  )*SK + k0    )*2);
            qfh[mt][ks][1] = *(const uint32_t*)(sm + 73728 + ((r0+g+8)*SK + k0    )*2);
            qfh[mt][ks][2] = *(const uint32_t*)(sm + 73728 + ((r0+g  )*SK + k0 + 8)*2);
            qfh[mt][ks][3] = *(const uint32_t*)(sm + 73728 + ((r0+g+8)*SK + k0 + 8)*2);
            qfl[mt][ks][0] = *(const uint32_t*)(sm + 92160 + ((r0+g  )*SK + k0    )*2);
            qfl[mt][ks][1] = *(const uint32_t*)(sm + 92160 + ((r0+g+8)*SK + k0    )*2);
            qfl[mt][ks][2] = *(const uint32_t*)(sm + 92160 + ((r0+g  )*SK + k0 + 8)*2);
            qfl[mt][ks][3] = *(const uint32_t*)(sm + 92160 + ((r0+g+8)*SK + k0 + 8)*2);
        }
    }
    __syncthreads();          // P area free again

    kvload(smb, t, b, 0, 0);  // prefetch tile 0

    float O[2][4][4];
    float lac[2][2];
#pragma unroll
    for (int mt = 0; mt < 2; mt++){
        lac[mt][0] = lac[mt][1] = 0.f;
#pragma unroll
        for (int nt = 0; nt < 4; nt++)
#pragma unroll
            for (int u = 0; u < 4; u++) O[mt][nt][u] = 0.f;
    }

    for (int tt = 0; tt < 64; tt++){
        const int buf = tt & 1;
        CPWAIT0();
        __syncthreads();                       // K/V[buf] ready; P free
        if (tt < 63) kvload(smb, t, b, tt + 1, buf ^ 1);

        // ---- S = Q K^T (3-term split) ----
        float sc[2][4][4];
#pragma unroll
        for (int mt = 0; mt < 2; mt++)
#pragma unroll
            for (int nt = 0; nt < 4; nt++)
#pragma unroll
                for (int u = 0; u < 4; u++) sc[mt][nt][u] = 0.f;

        const char* KH = sm + buf*18432;
        const char* KL = KH + 9216;
#pragma unroll
        for (int ks = 0; ks < 4; ks++){
            const int k0 = ks*16 + 2*tig;
            uint32_t bh[4][2], bl[4][2];
#pragma unroll
            for (int nt = 0; nt < 4; nt++){
                int n = warpn*32 + nt*8 + g;
                bh[nt][0] = *(const uint32_t*)(KH + (n*SK + k0    )*2);
                bh[nt][1] = *(const uint32_t*)(KH + (n*SK + k0 + 8)*2);
                bl[nt][0] = *(const uint32_t*)(KL + (n*SK + k0    )*2);
                bl[nt][1] = *(const uint32_t*)(KL + (n*SK + k0 + 8)*2);
            }
#pragma unroll
            for (int mt = 0; mt < 2; mt++)
#pragma unroll
                for (int nt = 0; nt < 4; nt++){
                    mma_bf16(sc[mt][nt], qfh[mt][ks], bh[nt]);
                    mma_bf16(sc[mt][nt], qfl[mt][ks], bh[nt]);
                    mma_bf16(sc[mt][nt], qfh[mt][ks], bl[nt]);
                }
        }
        // ---- exp + mask, split P to smem ----
        char* PH = sm + 73728;
        char* PL = sm + 92160;
#pragma unroll
        for (int mt = 0; mt < 2; mt++){
            int r0 = warpm*32 + mt*16;
#pragma unroll
            for (int nt = 0; nt < 4; nt++){
                int c0 = warpn*32 + nt*8 + 2*tig;
                float x0 = sc[mt][nt][0]*0.125f, x1 = sc[mt][nt][1]*0.125f;
                float x2 = sc[mt][nt][2]*0.125f, x3 = sc[mt][nt][3]*0.125f;
                float p0 = (x0 == maskv) ? 0.f : __expf(x0);
                float p1 = (x1 == maskv) ? 0.f : __expf(x1);
                float p2 = (x2 == maskv) ? 0.f : __expf(x2);
                float p3 = (x3 == maskv) ? 0.f : __expf(x3);
                lac[mt][0] += p0 + p1;
                lac[mt][1] += p2 + p3;
                uint32_t lo, hi;
                hi = split2(p0, p1, lo);
                *(uint32_t*)(PH + ((r0+g  )*SK + c0)*2) = hi;
                *(uint32_t*)(PL + ((r0+g  )*SK + c0)*2) = lo;
                hi = split2(p2, p3, lo);
                *(uint32_t*)(PH + ((r0+g+8)*SK + c0)*2) = hi;
                *(uint32_t*)(PL + ((r0+g+8)*SK + c0)*2) = lo;
            }
        }
        __syncthreads();                       // P complete
        // ---- O += P V (3-term split) ----
        const char* VH = sm + 36864 + buf*18432;
        const char* VL = VH + 9216;
#pragma unroll
        for (int ks = 0; ks < 4; ks++){
            const int k0 = ks*16 + 2*tig;
            uint32_t ah[2][4], al[2][4], vh[4][2], vl[4][2];
#pragma unroll
            for (int mt = 0; mt < 2; mt++){
                int r0 = warpm*32 + mt*16;
                ah[mt][0] = *(const uint32_t*)(PH + ((r0+g  )*SK + k0    )*2);
                ah[mt][1] = *(const uint32_t*)(PH + ((r0+g+8)*SK + k0    )*2);
                ah[mt][2] = *(const uint32_t*)(PH + ((r0+g  )*SK + k0 + 8)*2);
                ah[mt][3] = *(const uint32_t*)(PH + ((r0+g+8)*SK + k0 + 8)*2);
                al[mt][0] = *(const uint32_t*)(PL + ((r0+g  )*SK + k0    )*2);
                al[mt][1] = *(const uint32_t*)(PL + ((r0+g+8)*SK + k0    )*2);
                al[mt][2] = *(const uint32_t*)(PL + ((r0+g  )*SK + k0 + 8)*2);
                al[mt][3] = *(const uint32_t*)(PL + ((r0+g+8)*SK + k0 + 8)*2);
            }
#pragma unroll
            for (int nt = 0; nt < 4; nt++){
                int n = warpn*32 + nt*8 + g;     // dv row of vt tile
                vh[nt][0] = *(const uint32_t*)(VH + (n*SK + k0    )*2);
                vh[nt][1] = *(const uint32_t*)(VH + (n*SK + k0 + 8)*2);
                vl[nt][0] = *(const uint32_t*)(VL + (n*SK + k0    )*2);
                vl[nt][1] = *(const uint32_t*)(VL + (n*SK + k0 + 8)*2);
            }
#pragma unroll
            for (int mt = 0; mt < 2; mt++)
#pragma unroll
                for (int nt = 0; nt < 4; nt++){
                    mma_bf16(O[mt][nt], ah[mt], vh[nt]);
                    mma_bf16(O[mt][nt], al[mt], vh[nt]);
                    mma_bf16(O[mt][nt], ah[mt], vl[nt]);
                }
        }
    }

    // ---- l reduction (quad shfl + cross-warp via shared atomics) ----
    float* lred = (float*)(sm + 110592);
#pragma unroll
    for (int mt = 0; mt < 2; mt++)
#pragma unroll
        for (int h = 0; h < 2; h++){
            float s = lac[mt][h];
            s += __shfl_xor_sync(0xffffffffu, s, 1);
            s += __shfl_xor_sync(0xffffffffu, s, 2);
            if (tig == 0) atomicAdd(&lred[warpm*32 + mt*16 + h*8 + g], s);
        }
    __syncthreads();
#pragma unroll
    for (int mt = 0; mt < 2; mt++){
        int r0 = warpm*32 + mt*16 + g;
        float i0 = 1.f / lred[r0], i1 = 1.f / lred[r0 + 8];
#pragma unroll
        for (int nt = 0; nt < 4; nt++){
            int c = warpn*32 + nt*8 + 2*tig;
            *(float2*)(out + (qbase + r0    )*DKV + c) = make_float2(O[mt][nt][0]*i0, O[mt][nt][1]*i0);
            *(float2*)(out + (qbase + r0 + 8)*DKV + c) = make_float2(O[mt][nt][2]*i1, O[mt][nt][3]*i1);
        }
    }
}

// ---------------------------------------------------------------------------
extern "C" void kernel_launch(void* const* d_in, const int* in_sizes, int n_in,
                              void* d_out, int out_size)
{
    const float* q  = (const float*)d_in[0];
    const float* k  = (const float*)d_in[1];
    const float* v  = (const float*)d_in[2];
    const float* Wq = (const float*)d_in[3];
    const float* bq = (const float*)d_in[4];
    const float* Wk = (const float*)d_in[5];
    const float* bk = (const float*)d_in[6];
    const float* Wv = (const float*)d_in[7];
    const float* bv = (const float*)d_in[8];
    const int*   mk = (const int*)d_in[9];
    float* out = (float*)d_out;

    cudaFuncSetAttribute(projm,  cudaFuncAttributeMaxDynamicSharedMemorySize, P_SMEM);
    cudaFuncSetAttribute(flashm, cudaFuncAttributeMaxDynamicSharedMemorySize, F_SMEM);

    projm<<<dim3(ROWS/128, 1, 3), 256, P_SMEM>>>(q, k, v, Wq, bq, Wk, bk, Wv, bv);
    flashm<<<dim3(SEQ/128, NB), 256, F_SMEM>>>(mk, out);
}